// round 10
// baseline (speedup 1.0000x reference)
#include <cuda_runtime.h>
#include <math.h>
#include <stdint.h>
#include <stddef.h>

// Shapes: x:[32,32768] W1:[32768,2048] b1:[2048] W2:[2048,65536] b2:[65536]
// h = gelu(x@W1+b1); y = h@W2+b2 -> [32][2048][32]; out = batched QR(y).Q

#define NB    32
#define K1    32768
#define HID   2048
#define NOUT  65536
#define NCOL  256
#define NS1   32           // split-K for GEMM1 (chunk 1024)
#define KSTG  16           // k-rows per stage

// ---------------- static device scratch (no allocations) --------------------
__device__ float    g_part1[NS1 * NB * HID];          // 8 MB
__device__ uint32_t g_xp_hi[NB * (K1 / 2)];           // packed bf16x2 of x
__device__ uint32_t g_xp_lo[NB * (K1 / 2)];
__device__ uint32_t g_hp_hi[NB * (HID / 2)];          // packed bf16x2 of h
__device__ uint32_t g_hp_lo[NB * (HID / 2)];
__device__ float    g_y[NB * NOUT];                   // 8 MB
__device__ float    g_Gp[NB * 4 * 1024];
__device__ float    g_P[NB * 1024];
__device__ float    g_Qc[NB * 1024];

// ---------------- smem constants ---------------------------------------------
#define A_ROWSTR  12                               // u32 stride (8 data + 4 pad)
#define A_HI_U    (32 * A_ROWSTR)                  // 384 u32
#define ASLOT_U   (2 * A_HI_U)                     // 768 u32 (hi + lo)
#define WP_STRIDE 264                              // u32 per row (256 + 8 pad)
#define WPROWS    (KSTG / 2)                       // 8 pair-rows
#define WPBUF_U   (2 * WPROWS * WP_STRIDE)         // 4224 u32 (hi + lo)

// ---------------- helpers ----------------------------------------------------
__device__ __forceinline__ uint32_t smem_u32(const void* p) {
    uint32_t a;
    asm("{ .reg .u64 t; cvta.to.shared.u64 t, %1; cvt.u32.u64 %0, t; }"
        : "=r"(a) : "l"(p));
    return a;
}
// pack two fp32 -> bf16x2, LOW half = first (lower-k) element
__device__ __forceinline__ uint32_t pack_bf16(float lo_elt, float hi_elt) {
    uint32_t r;
    asm("cvt.rn.bf16x2.f32 %0, %1, %2;" : "=r"(r) : "f"(hi_elt), "f"(lo_elt));
    return r;
}
// split (x0,x1) into hi bf16x2 and lo bf16x2 (x = hi + lo + O(2^-17))
__device__ __forceinline__ void split2(float x0, float x1,
                                       uint32_t& hi, uint32_t& lo) {
    uint32_t h = pack_bf16(x0, x1);
    float h0 = __uint_as_float(h << 16);
    float h1 = __uint_as_float(h & 0xFFFF0000u);
    lo = pack_bf16(x0 - h0, x1 - h1);
    hi = h;
}
__device__ __forceinline__ void mma16816(float* c, const uint32_t* a,
                                         const uint32_t* b) {
    asm volatile(
        "mma.sync.aligned.m16n8k16.row.col.f32.bf16.bf16.f32 "
        "{%0,%1,%2,%3}, {%4,%5,%6,%7}, {%8,%9}, {%0,%1,%2,%3};"
        : "+f"(c[0]), "+f"(c[1]), "+f"(c[2]), "+f"(c[3])
        : "r"(a[0]), "r"(a[1]), "r"(a[2]), "r"(a[3]), "r"(b[0]), "r"(b[1]));
}
__device__ __forceinline__ void cp16(uint32_t saddr, const void* g) {
    asm volatile("cp.async.cg.shared.global [%0], [%1], 16;\n"
                 :: "r"(saddr), "l"(g));
}

// ---------------- pack x -> split bf16x2 pairs -------------------------------
__global__ void __launch_bounds__(256) pack_x(const float* __restrict__ x) {
    int gid = blockIdx.x * 256 + threadIdx.x;        // m*16384 + kp
    float2 v = *(const float2*)&x[(size_t)2 * gid];
    uint32_t h, l;
    split2(v.x, v.y, h, l);
    g_xp_hi[gid] = h;
    g_xp_lo[gid] = l;
}

// ---------------- GEMM: tensor cores; W LDG->regs->split->STS packed ---------
// WHICH==0: out partials to g_part1 (split-K over grid.y)
// WHICH==1: out y = acc + b2 directly (single K pass)
template<int N, int KTOT, int KC, int WHICH>
__global__ void __launch_bounds__(256, 2) mma_gemm(const float* __restrict__ W,
                                                   const float* __restrict__ bias) {
    __shared__ uint32_t sA[4 * ASLOT_U];             // 12288 B, 4-slot A ring
    __shared__ uint32_t sWP[2 * WPBUF_U];            // 33792 B, double-buffered W

    const int t = threadIdx.x;
    const int warp = t >> 5, lane = t & 31;
    const int g = lane >> 2, q = lane & 3;
    const int c0 = blockIdx.x * NCOL;
    const int s = blockIdx.y;
    const int k0 = s * KC;
    const int NSTEP = KC / KSTG;
    const int RS = KTOT / 2;                          // u32 per packed A row
    const uint32_t* Agh = (WHICH == 0) ? g_xp_hi : g_hp_hi;
    const uint32_t* Agl = (WHICH == 0) ? g_xp_lo : g_hp_lo;
    const uint32_t sA_base = smem_u32(sA);

    // ---- A stage loader (threads 0..127, 2 KB/stage via cp.async) ----
    auto load_A = [&](int st) {
        if (t < 128) {
            int which = t >> 6;                       // 0: hi, 1: lo
            int rr = (t >> 1) & 31, cc = t & 1;
            const uint32_t* src = which ? Agl : Agh;
            cp16(sA_base + ((st & 3) * ASLOT_U + which * A_HI_U
                     + rr * A_ROWSTR) * 4 + cc * 16,
                 &src[(size_t)rr * RS + (k0 >> 1) + st * (KSTG / 2) + cc * 4]);
        }
    };
    // ---- W stage: direct LDG into regs (coalesced float4 pairs) ----
    float4 ev[2], ov[2];
    auto load_W = [&](int st) {
#pragma unroll
        for (int i = 0; i < 2; i++) {
            int id = i * 256 + t;                     // 0..511
            int pr = id >> 6, c4 = id & 63;           // pr = k/2 (0..7)
            const float* base = &W[(size_t)(k0 + st * KSTG + 2 * pr) * N
                                   + c0 + c4 * 4];
            ev[i] = *(const float4*)base;             // even k row
            ov[i] = *(const float4*)(base + N);       // odd  k row
        }
    };
    // ---- split regs -> packed bf16x2 hi/lo in smem buffer (st&1) ----
    auto store_W = [&](int st) {
        uint32_t* dh = &sWP[(st & 1) * WPBUF_U];
        uint32_t* dl = dh + WPROWS * WP_STRIDE;
#pragma unroll
        for (int i = 0; i < 2; i++) {
            int id = i * 256 + t;
            int pr = id >> 6, c4 = id & 63;
            uint32_t h[4], l[4];
            split2(ev[i].x, ov[i].x, h[0], l[0]);
            split2(ev[i].y, ov[i].y, h[1], l[1]);
            split2(ev[i].z, ov[i].z, h[2], l[2]);
            split2(ev[i].w, ov[i].w, h[3], l[3]);
            int base = pr * WP_STRIDE + c4 * 4;
            *(uint4*)&dh[base] = make_uint4(h[0], h[1], h[2], h[3]);
            *(uint4*)&dl[base] = make_uint4(l[0], l[1], l[2], l[3]);
        }
    };

    // ---- prologue: 3 A stages committed; W stage 0 loaded + converted ----
    load_A(0); asm volatile("cp.async.commit_group;\n");
    load_A(1); asm volatile("cp.async.commit_group;\n");
    load_A(2); asm volatile("cp.async.commit_group;\n");
    load_W(0);
    store_W(0);
    asm volatile("cp.async.wait_group %0;\n" :: "n"(2));  // A0 landed
    __syncthreads();

    float acc[2][4][4];
#pragma unroll
    for (int mt = 0; mt < 2; mt++)
#pragma unroll
        for (int nt = 0; nt < 4; nt++)
#pragma unroll
            for (int i = 0; i < 4; i++) acc[mt][nt][i] = 0.f;

#pragma unroll 1
    for (int st = 0; st < NSTEP; st++) {
        if (st + 1 < NSTEP) load_W(st + 1);           // LDGs in flight over MMA
        if (st + 3 < NSTEP) load_A(st + 3);           // slot (st+3)&3: freed last iter
        asm volatile("cp.async.commit_group;\n");      // commit EVERY iter (FIFO)

        // ---- MMA on stage st ----
        const uint32_t* Ash = &sA[(st & 3) * ASLOT_U];
        const uint32_t* Asl = Ash + A_HI_U;
        const uint32_t* wph = &sWP[(st & 1) * WPBUF_U];
        const uint32_t* wpl = wph + WPROWS * WP_STRIDE;
        uint32_t ah[2][4], al[2][4];
#pragma unroll
        for (int mt = 0; mt < 2; mt++) {
            int mb = mt * 16;
            ah[mt][0] = Ash[(mb + g) * A_ROWSTR + q];
            ah[mt][1] = Ash[(mb + g + 8) * A_ROWSTR + q];
            ah[mt][2] = Ash[(mb + g) * A_ROWSTR + q + 4];
            ah[mt][3] = Ash[(mb + g + 8) * A_ROWSTR + q + 4];
            al[mt][0] = Asl[(mb + g) * A_ROWSTR + q];
            al[mt][1] = Asl[(mb + g + 8) * A_ROWSTR + q];
            al[mt][2] = Asl[(mb + g) * A_ROWSTR + q + 4];
            al[mt][3] = Asl[(mb + g + 8) * A_ROWSTR + q + 4];
        }
#pragma unroll
        for (int nt = 0; nt < 4; nt++) {
            int nc = warp * 32 + nt * 8 + g;
            uint32_t bh[2], bl[2];
            bh[0] = wph[q * WP_STRIDE + nc];
            bh[1] = wph[(q + 4) * WP_STRIDE + nc];
            bl[0] = wpl[q * WP_STRIDE + nc];
            bl[1] = wpl[(q + 4) * WP_STRIDE + nc];
#pragma unroll
            for (int mt = 0; mt < 2; mt++) {
                mma16816(acc[mt][nt], ah[mt], bh);   // hi*hi
                mma16816(acc[mt][nt], ah[mt], bl);   // hi*lo
                mma16816(acc[mt][nt], al[mt], bh);   // lo*hi
            }
        }

        if (st + 1 < NSTEP) store_W(st + 1);          // consumes LDG regs
        asm volatile("cp.async.wait_group %0;\n" :: "n"(2));  // A[st+1] landed
        __syncthreads();                               // WP/A visible for next iter
    }

    // ---- store ----
#pragma unroll
    for (int mt = 0; mt < 2; mt++)
#pragma unroll
        for (int nt = 0; nt < 4; nt++) {
            int m = mt * 16 + g;
            int n = c0 + warp * 32 + nt * 8 + 2 * q;
            if (WHICH == 0) {
                size_t b0 = ((size_t)(s * 32 + m)) * N + n;
                g_part1[b0]     = acc[mt][nt][0];
                g_part1[b0 + 1] = acc[mt][nt][1];
                size_t b1 = b0 + (size_t)8 * N;
                g_part1[b1]     = acc[mt][nt][2];
                g_part1[b1 + 1] = acc[mt][nt][3];
            } else {
                float bb0 = bias[n], bb1 = bias[n + 1];
                size_t b0 = (size_t)m * N + n;
                g_y[b0]     = acc[mt][nt][0] + bb0;
                g_y[b0 + 1] = acc[mt][nt][1] + bb1;
                size_t b1 = b0 + (size_t)8 * N;
                g_y[b1]     = acc[mt][nt][2] + bb0;
                g_y[b1 + 1] = acc[mt][nt][3] + bb1;
            }
        }
}

// ---------------- reduce + bias + exact GELU -> packed h ---------------------
__global__ void __launch_bounds__(256) reduce_gelu(const float* __restrict__ b1) {
    int gid = blockIdx.x * 256 + threadIdx.x;        // m*1024 + kp
    int m = gid >> 10, kp = gid & 1023;
    float2 sum = *(const float2*)&b1[2 * kp];
#pragma unroll 8
    for (int s = 0; s < NS1; s++) {
        float2 v = *(const float2*)&g_part1[((size_t)(s * 32 + m)) * HID + 2 * kp];
        sum.x += v.x; sum.y += v.y;
    }
    float h0 = 0.5f * sum.x * (1.0f + erff(sum.x * 0.70710678118654752f));
    float h1 = 0.5f * sum.y * (1.0f + erff(sum.y * 0.70710678118654752f));
    uint32_t h, l;
    split2(h0, h1, h, l);
    g_hp_hi[gid] = h;
    g_hp_lo[gid] = l;
}

// ---------------- Gram partials: Gp[b*4+s] = A_chunk^T A_chunk ---------------
__global__ void __launch_bounds__(256) gram_kernel() {
    __shared__ __align__(16) float sh[64][36];
    const int b = blockIdx.x >> 2, s = blockIdx.x & 3;
    const int t = threadIdx.x;
    const int i  = t >> 3;
    const int j0 = (t * 4) & 31;
    float a0 = 0.f, a1 = 0.f, a2 = 0.f, a3 = 0.f;
    for (int chunk = 0; chunk < 8; chunk++) {
        int rowbase = s * 512 + chunk * 64;
#pragma unroll
        for (int l = 0; l < 8; l++) {
            int idx = l * 256 + t;
            int rl = idx >> 5, c = idx & 31;
            sh[rl][c] = g_y[(size_t)b * NOUT + (rowbase + rl) * 32 + c];
        }
        __syncthreads();
#pragma unroll 16
        for (int kk = 0; kk < 64; kk++) {
            float ai = sh[kk][i];
            float4 aj = *reinterpret_cast<const float4*>(&sh[kk][j0]);
            a0 += ai * aj.x; a1 += ai * aj.y; a2 += ai * aj.z; a3 += ai * aj.w;
        }
        __syncthreads();
    }
    size_t o = (size_t)(b * 4 + s) * 1024 + i * 32 + j0;
    g_Gp[o] = a0; g_Gp[o + 1] = a1; g_Gp[o + 2] = a2; g_Gp[o + 3] = a3;
}

// ---------------- Householder QR recurrence in 64-dim coefficient space ------
// One warp per batch; thread t's rows of G and T cached in registers.
__global__ void __launch_bounds__(32) qr_recur() {
    const int b = blockIdx.x;
    const int t = threadIdx.x;
    __shared__ float sT[32][33];
    __shared__ float Vp[32][32], Vq[32][32], GH[32][32], TH[32][32];
    __shared__ float stau[32];
    __shared__ float pj[32], qj[32], spv[32], sqv[32];

    float rG[32], rT[32];
    for (int j = 0; j < 32; j++) {
        float g = 0.f;
#pragma unroll
        for (int s = 0; s < 4; s++) g += g_Gp[(size_t)(b * 4 + s) * 1024 + t * 32 + j];
        rG[j] = g;
        float tv = g_y[(size_t)b * NOUT + t * 32 + j];
        rT[j] = tv;
        sT[t][j] = tv;
    }
    __syncwarp();

    float p[32], q[32];
#pragma unroll
    for (int r = 0; r < 32; r++) { p[r] = (r == t) ? 1.f : 0.f; q[r] = 0.f; }

    for (int j = 0; j < 32; j++) {
        if (t == j) {
#pragma unroll
            for (int r = 0; r < 32; r++) { pj[r] = p[r]; qj[r] = q[r]; }
        }
        __syncwarp();
        float u = 0.f, gp = 0.f;
#pragma unroll
        for (int r = 0; r < 32; r++) { u += rT[r] * pj[r]; gp += rG[r] * pj[r]; }
        float h = u + qj[t];
        float term  = pj[t] * gp + qj[t] * (2.f * u + qj[t]);
        float hterm = (t < j) ? h * h : 0.f;
#pragma unroll
        for (int off = 16; off; off >>= 1) {
            term  += __shfl_xor_sync(0xffffffffu, term, off);
            hterm += __shfl_xor_sync(0xffffffffu, hterm, off);
        }
        float sigma = term - hterm;
        float alpha = __shfl_sync(0xffffffffu, h, j);
        float nrm = sqrtf(fmaxf(sigma, 0.f));
        float beta = (alpha >= 0.f) ? -nrm : nrm;
        float inv  = 1.f / (alpha - beta);
        float tauj = (beta - alpha) / beta;
        float pv = pj[t] * inv;
        float qv;
        if (t < j)       qv = (qj[t] - h) * inv;
        else if (t == j) qv = (qj[t] - beta) * inv;
        else             qv = qj[t] * inv;
        spv[t] = pv; sqv[t] = qv;
        Vp[j][t] = pv; Vq[j][t] = qv;
        if (t == 0) stau[j] = tauj;
        __syncwarp();
        float tpv = 0.f, gpv = 0.f, ttqv = 0.f;
#pragma unroll
        for (int r = 0; r < 32; r++) {
            tpv  += rT[r] * spv[r];
            gpv  += rG[r] * spv[r];
            ttqv += sT[r][t] * sqv[r];
        }
        GH[j][t] = gpv + ttqv;
        TH[j][t] = tpv + sqv[t];
        __syncwarp();
        if (t > j) {
            float w = 0.f;
#pragma unroll
            for (int r = 0; r < 32; r++) w += GH[j][r] * p[r] + TH[j][r] * q[r];
            float sc = tauj * w;
#pragma unroll
            for (int r = 0; r < 32; r++) { p[r] -= sc * Vp[j][r]; q[r] -= sc * Vq[j][r]; }
        }
        __syncwarp();
    }

#pragma unroll
    for (int r = 0; r < 32; r++) { p[r] = 0.f; q[r] = (r == t) ? 1.f : 0.f; }
    for (int j = 31; j >= 0; j--) {
        float w = 0.f;
#pragma unroll
        for (int r = 0; r < 32; r++) w += GH[j][r] * p[r] + TH[j][r] * q[r];
        float sc = stau[j] * w;
#pragma unroll
        for (int r = 0; r < 32; r++) { p[r] -= sc * Vp[j][r]; q[r] -= sc * Vq[j][r]; }
    }
#pragma unroll
    for (int r = 0; r < 32; r++) {
        g_P [(size_t)b * 1024 + r * 32 + t] = p[r];
        g_Qc[(size_t)b * 1024 + r * 32 + t] = q[r];
    }
}

// ---------------- Q = A P + E Qc ---------------------------------------------
__global__ void __launch_bounds__(256) formq(float* __restrict__ out) {
    __shared__ float sA[64][33];
    __shared__ float sP[32][33], sQ[32][33];
    const int b = blockIdx.y, rb = blockIdx.x;
    const int t = threadIdx.x;
    const int w = t >> 5, lane = t & 31;
#pragma unroll
    for (int l = 0; l < 8; l++) {
        int idx = l * 256 + t;
        int rl = idx >> 5, c = idx & 31;
        sA[rl][c] = g_y[(size_t)b * NOUT + (rb * 64 + rl) * 32 + c];
    }
#pragma unroll
    for (int l = 0; l < 4; l++) {
        int idx = l * 256 + t;
        int k = idx >> 5, c = idx & 31;
        sP[k][c] = g_P [(size_t)b * 1024 + idx];
        sQ[k][c] = g_Qc[(size_t)b * 1024 + idx];
    }
    __syncthreads();
#pragma unroll
    for (int rr = 0; rr < 8; rr++) {
        int rl = w * 8 + rr;
        float acc = 0.f;
#pragma unroll
        for (int k = 0; k < 32; k++) acc += sA[rl][k] * sP[k][lane];
        int rg = rb * 64 + rl;
        if (rg < 32) acc += sQ[rg][lane];
        out[(size_t)b * NOUT + rg * 32 + lane] = acc;
    }
}

// ---------------- launch -----------------------------------------------------
extern "C" void kernel_launch(void* const* d_in, const int* in_sizes, int n_in,
                              void* d_out, int out_size) {
    const float* x  = (const float*)d_in[0];
    const float* W1 = (const float*)d_in[1];
    const float* b1 = (const float*)d_in[2];
    const float* W2 = (const float*)d_in[3];
    const float* b2 = (const float*)d_in[4];
    float* out = (float*)d_out;
    (void)in_sizes; (void)n_in; (void)out_size;

    pack_x<<<(NB * K1 / 2) / 256, 256>>>(x);
    mma_gemm<HID, K1, K1 / NS1, 0><<<dim3(HID / NCOL, NS1), 256>>>(W1, b1);
    reduce_gelu<<<(NB * HID / 2) / 256, 256>>>(b1);
    mma_gemm<NOUT, HID, HID, 1><<<dim3(NOUT / NCOL, 1), 256>>>(W2, b2);
    gram_kernel<<<NB * 4, 256>>>();
    qr_recur<<<NB, 32>>>();
    formq<<<dim3(32, NB), 256>>>(out);
}

// round 13
// speedup vs baseline: 1.1576x; 1.1576x over previous
#include <cuda_runtime.h>
#include <math.h>
#include <stdint.h>
#include <stddef.h>

// Shapes: x:[32,32768] W1:[32768,2048] b1:[2048] W2:[2048,65536] b2:[65536]
// h = gelu(x@W1+b1); y = h@W2+b2 -> [32][2048][32]; out = batched QR(y).Q

#define NB    32
#define K1    32768
#define HID   2048
#define NOUT  65536
#define NCOL  256
#define NS1   32           // split-K for GEMM1 (chunk 1024)
#define DEPTH 4            // W/A cp.async ring depth (stages of 16 k-rows)
#define KSTG  16           // k-rows per stage

// ---------------- static device scratch (no allocations) --------------------
__device__ float    g_part1[NS1 * NB * HID];          // 8 MB
__device__ uint32_t g_xp_hi[NB * (K1 / 2)];           // packed bf16x2 of x
__device__ uint32_t g_xp_lo[NB * (K1 / 2)];
__device__ uint32_t g_hp_hi[NB * (HID / 2)];          // packed bf16x2 of h
__device__ uint32_t g_hp_lo[NB * (HID / 2)];
__device__ float    g_y[NB * NOUT];                   // 8 MB
__device__ float    g_Gp[NB * 4 * 1024];
__device__ float    g_P[NB * 1024];
__device__ float    g_Qc[NB * 1024];

// ---------------- smem constants ---------------------------------------------
#define W_RSTR    260                              // fp32 stride per k-row (+4 pad)
#define WSTG_U    (KSTG * W_RSTR)                  // 4160 floats per W stage
#define A_ROWSTR  12                               // u32 stride (8 data + 4 pad)
#define A_HI_U    (32 * A_ROWSTR)                  // 384 u32
#define ASLOT_U   (2 * A_HI_U)                     // 768 u32 (hi + lo)
// total: 4*16640 + 4*3072 = 78848 B -> 2 CTAs/SM

// ---------------- helpers ----------------------------------------------------
__device__ __forceinline__ uint32_t smem_u32(const void* p) {
    uint32_t a;
    asm("{ .reg .u64 t; cvta.to.shared.u64 t, %1; cvt.u32.u64 %0, t; }"
        : "=r"(a) : "l"(p));
    return a;
}
// pack two fp32 -> bf16x2, LOW half = first (lower-k) element
__device__ __forceinline__ uint32_t pack_bf16(float lo_elt, float hi_elt) {
    uint32_t r;
    asm("cvt.rn.bf16x2.f32 %0, %1, %2;" : "=r"(r) : "f"(hi_elt), "f"(lo_elt));
    return r;
}
// split (x0,x1) into hi bf16x2 and lo bf16x2 (x = hi + lo + O(2^-17))
__device__ __forceinline__ void split2(float x0, float x1,
                                       uint32_t& hi, uint32_t& lo) {
    uint32_t h = pack_bf16(x0, x1);
    float h0 = __uint_as_float(h << 16);
    float h1 = __uint_as_float(h & 0xFFFF0000u);
    lo = pack_bf16(x0 - h0, x1 - h1);
    hi = h;
}
__device__ __forceinline__ void mma16816(float* c, const uint32_t* a,
                                         const uint32_t* b) {
    asm volatile(
        "mma.sync.aligned.m16n8k16.row.col.f32.bf16.bf16.f32 "
        "{%0,%1,%2,%3}, {%4,%5,%6,%7}, {%8,%9}, {%0,%1,%2,%3};"
        : "+f"(c[0]), "+f"(c[1]), "+f"(c[2]), "+f"(c[3])
        : "r"(a[0]), "r"(a[1]), "r"(a[2]), "r"(a[3]), "r"(b[0]), "r"(b[1]));
}
__device__ __forceinline__ void cp16(uint32_t saddr, const void* g) {
    asm volatile("cp.async.cg.shared.global [%0], [%1], 16;\n"
                 :: "r"(saddr), "l"(g));
}

// ---------------- pack x -> split bf16x2 pairs -------------------------------
__global__ void __launch_bounds__(256) pack_x(const float* __restrict__ x) {
    int gid = blockIdx.x * 256 + threadIdx.x;        // m*16384 + kp
    float2 v = *(const float2*)&x[(size_t)2 * gid];
    uint32_t h, l;
    split2(v.x, v.y, h, l);
    g_xp_hi[gid] = h;
    g_xp_lo[gid] = l;
}

// ---------------- GEMM: tensor cores; W split at fragment-load time ----------
// WHICH==0: out partials to g_part1 (split-K over grid.y)
// WHICH==1: out y = acc + b2 directly (single K pass)
template<int N, int KTOT, int KC, int WHICH>
__global__ void __launch_bounds__(256, 2) mma_gemm(const float* __restrict__ W,
                                                   const float* __restrict__ bias) {
    __shared__ float    sW[DEPTH * WSTG_U];          // 66560 B, fp32 W ring
    __shared__ uint32_t sA[DEPTH * ASLOT_U];         // 12288 B, packed A ring

    const int t = threadIdx.x;
    const int warp = t >> 5, lane = t & 31;
    const int g = lane >> 2, q = lane & 3;
    const int c0 = blockIdx.x * NCOL;
    const int s = blockIdx.y;
    const int k0 = s * KC;
    const int NSTEP = KC / KSTG;
    const int RS = KTOT / 2;                          // u32 per packed A row
    const uint32_t* Agh = (WHICH == 0) ? g_xp_hi : g_hp_hi;
    const uint32_t* Agl = (WHICH == 0) ? g_xp_lo : g_hp_lo;
    const uint32_t sW_base = smem_u32(sW);
    const uint32_t sA_base = smem_u32(sA);

    // ---- combined stage loader (one commit group): W 16 KB + A 2 KB ----
    auto load_stage = [&](int st) {
#pragma unroll
        for (int i = 0; i < 4; i++) {
            int f = (i * 256 + t) * 4;                // 0..4092, step 4
            int r = f >> 8, c = f & 255;
            cp16(sW_base + ((st & 3) * WSTG_U + r * W_RSTR + c) * 4,
                 &W[(size_t)(k0 + st * KSTG + r) * N + (c0 + c)]);
        }
        if (t < 128) {
            int which = t >> 6;                       // 0: hi, 1: lo
            int rr = (t >> 1) & 31, cc = t & 1;
            const uint32_t* src = which ? Agl : Agh;
            cp16(sA_base + ((st & 3) * ASLOT_U + which * A_HI_U
                     + rr * A_ROWSTR) * 4 + cc * 16,
                 &src[(size_t)rr * RS + (k0 >> 1) + st * (KSTG / 2) + cc * 4]);
        }
    };

    // ---- prologue: stages 0..2 committed ----
#pragma unroll
    for (int d = 0; d < DEPTH - 1; d++) {
        load_stage(d);
        asm volatile("cp.async.commit_group;\n");
    }

    float acc[2][4][4];
#pragma unroll
    for (int mt = 0; mt < 2; mt++)
#pragma unroll
        for (int nt = 0; nt < 4; nt++)
#pragma unroll
            for (int i = 0; i < 4; i++) acc[mt][nt][i] = 0.f;

#pragma unroll 1
    for (int st = 0; st < NSTEP; st++) {
        // committed = 3+st; stage st complete when <=2 groups pending
        asm volatile("cp.async.wait_group %0;\n" :: "n"(2));
        __syncthreads();   // stage st visible; slot (st-1)&3 free for reuse

        if (st + 3 < NSTEP) load_stage(st + 3);       // writes slot (st-1)&3
        asm volatile("cp.async.commit_group;\n");      // commit EVERY iter (FIFO)

        // ---- MMA on stage st; B split inline from fp32 smem ----
        const uint32_t* Ash = &sA[(st & 3) * ASLOT_U];
        const uint32_t* Asl = Ash + A_HI_U;
        const float*    ws  = &sW[(st & 3) * WSTG_U];
        uint32_t ah[2][4], al[2][4];
#pragma unroll
        for (int mt = 0; mt < 2; mt++) {
            int mb = mt * 16;
            ah[mt][0] = Ash[(mb + g) * A_ROWSTR + q];
            ah[mt][1] = Ash[(mb + g + 8) * A_ROWSTR + q];
            ah[mt][2] = Ash[(mb + g) * A_ROWSTR + q + 4];
            ah[mt][3] = Ash[(mb + g + 8) * A_ROWSTR + q + 4];
            al[mt][0] = Asl[(mb + g) * A_ROWSTR + q];
            al[mt][1] = Asl[(mb + g + 8) * A_ROWSTR + q];
            al[mt][2] = Asl[(mb + g) * A_ROWSTR + q + 4];
            al[mt][3] = Asl[(mb + g + 8) * A_ROWSTR + q + 4];
        }
#pragma unroll
        for (int nt = 0; nt < 4; nt++) {
            int nc = warp * 32 + nt * 8 + g;
            // k rows for this lane: 2q, 2q+1 (pair 0) and 2q+8, 2q+9 (pair 1)
            float e0 = ws[(2 * q) * W_RSTR + nc];
            float o0 = ws[(2 * q + 1) * W_RSTR + nc];
            float e1 = ws[(2 * q + 8) * W_RSTR + nc];
            float o1 = ws[(2 * q + 9) * W_RSTR + nc];
            uint32_t bh[2], bl[2];
            split2(e0, o0, bh[0], bl[0]);
            split2(e1, o1, bh[1], bl[1]);
#pragma unroll
            for (int mt = 0; mt < 2; mt++) {
                mma16816(acc[mt][nt], ah[mt], bh);   // hi*hi
                mma16816(acc[mt][nt], ah[mt], bl);   // hi*lo
                mma16816(acc[mt][nt], al[mt], bh);   // lo*hi
            }
        }
    }

    // ---- store ----
#pragma unroll
    for (int mt = 0; mt < 2; mt++)
#pragma unroll
        for (int nt = 0; nt < 4; nt++) {
            int m = mt * 16 + g;
            int n = c0 + warp * 32 + nt * 8 + 2 * q;
            if (WHICH == 0) {
                size_t b0 = ((size_t)(s * 32 + m)) * N + n;
                g_part1[b0]     = acc[mt][nt][0];
                g_part1[b0 + 1] = acc[mt][nt][1];
                size_t b1 = b0 + (size_t)8 * N;
                g_part1[b1]     = acc[mt][nt][2];
                g_part1[b1 + 1] = acc[mt][nt][3];
            } else {
                float bb0 = bias[n], bb1 = bias[n + 1];
                size_t b0 = (size_t)m * N + n;
                g_y[b0]     = acc[mt][nt][0] + bb0;
                g_y[b0 + 1] = acc[mt][nt][1] + bb1;
                size_t b1 = b0 + (size_t)8 * N;
                g_y[b1]     = acc[mt][nt][2] + bb0;
                g_y[b1 + 1] = acc[mt][nt][3] + bb1;
            }
        }
}

// ---------------- reduce + bias + exact GELU -> packed h ---------------------
__global__ void __launch_bounds__(256) reduce_gelu(const float* __restrict__ b1) {
    int gid = blockIdx.x * 256 + threadIdx.x;        // m*1024 + kp
    int m = gid >> 10, kp = gid & 1023;
    float2 sum = *(const float2*)&b1[2 * kp];
#pragma unroll 8
    for (int s = 0; s < NS1; s++) {
        float2 v = *(const float2*)&g_part1[((size_t)(s * 32 + m)) * HID + 2 * kp];
        sum.x += v.x; sum.y += v.y;
    }
    float h0 = 0.5f * sum.x * (1.0f + erff(sum.x * 0.70710678118654752f));
    float h1 = 0.5f * sum.y * (1.0f + erff(sum.y * 0.70710678118654752f));
    uint32_t h, l;
    split2(h0, h1, h, l);
    g_hp_hi[gid] = h;
    g_hp_lo[gid] = l;
}

// ---------------- Gram partials: Gp[b*4+s] = A_chunk^T A_chunk ---------------
__global__ void __launch_bounds__(256) gram_kernel() {
    __shared__ __align__(16) float sh[64][36];
    const int b = blockIdx.x >> 2, s = blockIdx.x & 3;
    const int t = threadIdx.x;
    const int i  = t >> 3;
    const int j0 = (t * 4) & 31;
    float a0 = 0.f, a1 = 0.f, a2 = 0.f, a3 = 0.f;
    for (int chunk = 0; chunk < 8; chunk++) {
        int rowbase = s * 512 + chunk * 64;
#pragma unroll
        for (int l = 0; l < 8; l++) {
            int idx = l * 256 + t;
            int rl = idx >> 5, c = idx & 31;
            sh[rl][c] = g_y[(size_t)b * NOUT + (rowbase + rl) * 32 + c];
        }
        __syncthreads();
#pragma unroll 16
        for (int kk = 0; kk < 64; kk++) {
            float ai = sh[kk][i];
            float4 aj = *reinterpret_cast<const float4*>(&sh[kk][j0]);
            a0 += ai * aj.x; a1 += ai * aj.y; a2 += ai * aj.z; a3 += ai * aj.w;
        }
        __syncthreads();
    }
    size_t o = (size_t)(b * 4 + s) * 1024 + i * 32 + j0;
    g_Gp[o] = a0; g_Gp[o + 1] = a1; g_Gp[o + 2] = a2; g_Gp[o + 3] = a3;
}

// ---------------- Householder QR recurrence in 64-dim coefficient space ------
__global__ void __launch_bounds__(32) qr_recur() {
    const int b = blockIdx.x;
    const int t = threadIdx.x;
    __shared__ float sT[32][33];
    __shared__ float Vp[32][32], Vq[32][32], GH[32][32], TH[32][32];
    __shared__ float stau[32];
    __shared__ float pj[32], qj[32], spv[32], sqv[32];

    float rG[32], rT[32];
    for (int j = 0; j < 32; j++) {
        float g = 0.f;
#pragma unroll
        for (int s = 0; s < 4; s++) g += g_Gp[(size_t)(b * 4 + s) * 1024 + t * 32 + j];
        rG[j] = g;
        float tv = g_y[(size_t)b * NOUT + t * 32 + j];
        rT[j] = tv;
        sT[t][j] = tv;
    }
    __syncwarp();

    float p[32], q[32];
#pragma unroll
    for (int r = 0; r < 32; r++) { p[r] = (r == t) ? 1.f : 0.f; q[r] = 0.f; }

    for (int j = 0; j < 32; j++) {
        if (t == j) {
#pragma unroll
            for (int r = 0; r < 32; r++) { pj[r] = p[r]; qj[r] = q[r]; }
        }
        __syncwarp();
        float u = 0.f, gp = 0.f;
#pragma unroll
        for (int r = 0; r < 32; r++) { u += rT[r] * pj[r]; gp += rG[r] * pj[r]; }
        float h = u + qj[t];
        float term  = pj[t] * gp + qj[t] * (2.f * u + qj[t]);
        float hterm = (t < j) ? h * h : 0.f;
#pragma unroll
        for (int off = 16; off; off >>= 1) {
            term  += __shfl_xor_sync(0xffffffffu, term, off);
            hterm += __shfl_xor_sync(0xffffffffu, hterm, off);
        }
        float sigma = term - hterm;
        float alpha = __shfl_sync(0xffffffffu, h, j);
        float nrm = sqrtf(fmaxf(sigma, 0.f));
        float beta = (alpha >= 0.f) ? -nrm : nrm;
        float inv  = 1.f / (alpha - beta);
        float tauj = (beta - alpha) / beta;
        float pv = pj[t] * inv;
        float qv;
        if (t < j)       qv = (qj[t] - h) * inv;
        else if (t == j) qv = (qj[t] - beta) * inv;
        else             qv = qj[t] * inv;
        spv[t] = pv; sqv[t] = qv;
        Vp[j][t] = pv; Vq[j][t] = qv;
        if (t == 0) stau[j] = tauj;
        __syncwarp();
        float tpv = 0.f, gpv = 0.f, ttqv = 0.f;
#pragma unroll
        for (int r = 0; r < 32; r++) {
            tpv  += rT[r] * spv[r];
            gpv  += rG[r] * spv[r];
            ttqv += sT[r][t] * sqv[r];
        }
        GH[j][t] = gpv + ttqv;
        TH[j][t] = tpv + sqv[t];
        __syncwarp();
        if (t > j) {
            float w = 0.f;
#pragma unroll
            for (int r = 0; r < 32; r++) w += GH[j][r] * p[r] + TH[j][r] * q[r];
            float sc = tauj * w;
#pragma unroll
            for (int r = 0; r < 32; r++) { p[r] -= sc * Vp[j][r]; q[r] -= sc * Vq[j][r]; }
        }
        __syncwarp();
    }

#pragma unroll
    for (int r = 0; r < 32; r++) { p[r] = 0.f; q[r] = (r == t) ? 1.f : 0.f; }
    for (int j = 31; j >= 0; j--) {
        float w = 0.f;
#pragma unroll
        for (int r = 0; r < 32; r++) w += GH[j][r] * p[r] + TH[j][r] * q[r];
        float sc = stau[j] * w;
#pragma unroll
        for (int r = 0; r < 32; r++) { p[r] -= sc * Vp[j][r]; q[r] -= sc * Vq[j][r]; }
    }
#pragma unroll
    for (int r = 0; r < 32; r++) {
        g_P [(size_t)b * 1024 + r * 32 + t] = p[r];
        g_Qc[(size_t)b * 1024 + r * 32 + t] = q[r];
    }
}

// ---------------- Q = A P + E Qc ---------------------------------------------
__global__ void __launch_bounds__(256) formq(float* __restrict__ out) {
    __shared__ float sA[64][33];
    __shared__ float sP[32][33], sQ[32][33];
    const int b = blockIdx.y, rb = blockIdx.x;
    const int t = threadIdx.x;
    const int w = t >> 5, lane = t & 31;
#pragma unroll
    for (int l = 0; l < 8; l++) {
        int idx = l * 256 + t;
        int rl = idx >> 5, c = idx & 31;
        sA[rl][c] = g_y[(size_t)b * NOUT + (rb * 64 + rl) * 32 + c];
    }
#pragma unroll
    for (int l = 0; l < 4; l++) {
        int idx = l * 256 + t;
        int k = idx >> 5, c = idx & 31;
        sP[k][c] = g_P [(size_t)b * 1024 + idx];
        sQ[k][c] = g_Qc[(size_t)b * 1024 + idx];
    }
    __syncthreads();
#pragma unroll
    for (int rr = 0; rr < 8; rr++) {
        int rl = w * 8 + rr;
        float acc = 0.f;
#pragma unroll
        for (int k = 0; k < 32; k++) acc += sA[rl][k] * sP[k][lane];
        int rg = rb * 64 + rl;
        if (rg < 32) acc += sQ[rg][lane];
        out[(size_t)b * NOUT + rg * 32 + lane] = acc;
    }
}

// ---------------- launch -----------------------------------------------------
extern "C" void kernel_launch(void* const* d_in, const int* in_sizes, int n_in,
                              void* d_out, int out_size) {
    const float* x  = (const float*)d_in[0];
    const float* W1 = (const float*)d_in[1];
    const float* b1 = (const float*)d_in[2];
    const float* W2 = (const float*)d_in[3];
    const float* b2 = (const float*)d_in[4];
    float* out = (float*)d_out;
    (void)in_sizes; (void)n_in; (void)out_size;

    pack_x<<<(NB * K1 / 2) / 256, 256>>>(x);
    mma_gemm<HID, K1, K1 / NS1, 0><<<dim3(HID / NCOL, NS1), 256>>>(W1, b1);
    reduce_gelu<<<(NB * HID / 2) / 256, 256>>>(b1);
    mma_gemm<NOUT, HID, HID, 1><<<dim3(NOUT / NCOL, 1), 256>>>(W2, b2);
    gram_kernel<<<NB * 4, 256>>>();
    qr_recur<<<NB, 32>>>();
    formq<<<dim3(32, NB), 256>>>(out);
}

// round 14
// speedup vs baseline: 1.1913x; 1.0291x over previous
#include <cuda_runtime.h>
#include <math.h>
#include <stdint.h>
#include <stddef.h>

// Shapes: x:[32,32768] W1:[32768,2048] b1:[2048] W2:[2048,65536] b2:[65536]
// h = gelu(x@W1+b1); y = h@W2+b2 -> [32][2048][32]; out = batched QR(y).Q

#define NB    32
#define K1    32768
#define HID   2048
#define NOUT  65536
#define NCOL  256
#define NS1   32           // split-K for GEMM1 (chunk 1024)
#define KSTG  16           // k-rows per stage
#define WDEPTH 6           // W ring slots (pair processing needs 6)

// ---------------- static device scratch (no allocations) --------------------
__device__ float    g_part1[NS1 * NB * HID];          // 8 MB
__device__ uint32_t g_xp_hi[NB * (K1 / 2)];           // packed bf16x2 of x
__device__ uint32_t g_xp_lo[NB * (K1 / 2)];
__device__ uint32_t g_hp_hi[NB * (HID / 2)];          // packed bf16x2 of h
__device__ uint32_t g_hp_lo[NB * (HID / 2)];
__device__ float    g_y[NB * NOUT];                   // 8 MB
__device__ float    g_Gp[NB * 4 * 1024];
__device__ float    g_P[NB * 1024];
__device__ float    g_Qc[NB * 1024];

// ---------------- smem constants ---------------------------------------------
#define W_RSTR    260                              // fp32 stride per k-row (+4 pad)
#define WSTG_U    (KSTG * W_RSTR)                  // 4160 floats per W stage
#define A_RSTR    36                               // u32/row: 16 hi + 16 lo + 4 pad
#define ASS_U     (32 * A_RSTR)                    // 1152 u32 per A superslot (2 stages)
// totals: W 6*16640=99840 B + A 3*4608=13824 B = 113664 B -> 2 CTAs/SM (<=114688)

// ---------------- helpers ----------------------------------------------------
__device__ __forceinline__ uint32_t smem_u32(const void* p) {
    uint32_t a;
    asm("{ .reg .u64 t; cvta.to.shared.u64 t, %1; cvt.u32.u64 %0, t; }"
        : "=r"(a) : "l"(p));
    return a;
}
// pack two fp32 -> bf16x2, LOW half = first (lower-k) element
__device__ __forceinline__ uint32_t pack_bf16(float lo_elt, float hi_elt) {
    uint32_t r;
    asm("cvt.rn.bf16x2.f32 %0, %1, %2;" : "=r"(r) : "f"(hi_elt), "f"(lo_elt));
    return r;
}
// split (x0,x1) into hi bf16x2 and lo bf16x2 (x = hi + lo + O(2^-17))
__device__ __forceinline__ void split2(float x0, float x1,
                                       uint32_t& hi, uint32_t& lo) {
    uint32_t h = pack_bf16(x0, x1);
    float h0 = __uint_as_float(h << 16);
    float h1 = __uint_as_float(h & 0xFFFF0000u);
    lo = pack_bf16(x0 - h0, x1 - h1);
    hi = h;
}
__device__ __forceinline__ void mma16816(float* c, const uint32_t* a,
                                         const uint32_t* b) {
    asm volatile(
        "mma.sync.aligned.m16n8k16.row.col.f32.bf16.bf16.f32 "
        "{%0,%1,%2,%3}, {%4,%5,%6,%7}, {%8,%9}, {%0,%1,%2,%3};"
        : "+f"(c[0]), "+f"(c[1]), "+f"(c[2]), "+f"(c[3])
        : "r"(a[0]), "r"(a[1]), "r"(a[2]), "r"(a[3]), "r"(b[0]), "r"(b[1]));
}
__device__ __forceinline__ void cp16(uint32_t saddr, const void* g) {
    asm volatile("cp.async.cg.shared.global [%0], [%1], 16;\n"
                 :: "r"(saddr), "l"(g));
}

// ---------------- pack x -> split bf16x2 pairs -------------------------------
__global__ void __launch_bounds__(256) pack_x(const float* __restrict__ x) {
    int gid = blockIdx.x * 256 + threadIdx.x;        // m*16384 + kp
    float2 v = *(const float2*)&x[(size_t)2 * gid];
    uint32_t h, l;
    split2(v.x, v.y, h, l);
    g_xp_hi[gid] = h;
    g_xp_lo[gid] = l;
}

// ---------------- GEMM: tensor cores; pair-stage pipeline --------------------
// WHICH==0: out partials to g_part1 (split-K over grid.y)
// WHICH==1: out y = acc + b2 directly (single K pass)
template<int N, int KTOT, int KC, int WHICH>
__global__ void __launch_bounds__(256, 2) mma_gemm(const float* __restrict__ W,
                                                   const float* __restrict__ bias) {
    __shared__ float    sW[WDEPTH * WSTG_U];         // 99840 B, fp32 W ring
    __shared__ uint32_t sA[3 * ASS_U];               // 13824 B, packed A superslots

    const int t = threadIdx.x;
    const int warp = t >> 5, lane = t & 31;
    const int g = lane >> 2, q = lane & 3;
    const int c0 = blockIdx.x * NCOL;
    const int s = blockIdx.y;
    const int k0 = s * KC;
    const int NSTEP = KC / KSTG;                      // even
    const int NPAIR = NSTEP / 2;
    const int RS = KTOT / 2;                          // u32 per packed A row
    const uint32_t* Agh = (WHICH == 0) ? g_xp_hi : g_hp_hi;
    const uint32_t* Agl = (WHICH == 0) ? g_xp_lo : g_hp_lo;
    const uint32_t sW_base = smem_u32(sW);
    const uint32_t sA_base = smem_u32(sA);

    // ---- W stage loader: 16 KB via 4 cp16/thread ----
    auto load_W = [&](int st) {
#pragma unroll
        for (int i = 0; i < 4; i++) {
            int f = (i * 256 + t) * 4;                // 0..4092, step 4
            int r = f >> 8, c = f & 255;
            cp16(sW_base + ((st % WDEPTH) * WSTG_U + r * W_RSTR + c) * 4,
                 &W[(size_t)(k0 + st * KSTG + r) * N + (c0 + c)]);
        }
    };
    // ---- A superslot loader (2 stages = 16 u32 hi + 16 u32 lo per row) ----
    auto load_A = [&](int ss) {
        int row = t >> 3, seg = t & 7;
        int which = seg >> 2, cc = seg & 3;
        const uint32_t* src = which ? Agl : Agh;
        cp16(sA_base + ((ss % 3) * ASS_U + row * A_RSTR + which * 16 + cc * 4) * 4,
             &src[(size_t)row * RS + (k0 >> 1) + ss * 16 + cc * 4]);
    };

    // ---- prologue: W stages 0..3, A superslots 0..1; 4 commit groups ----
    load_W(0); load_A(0); asm volatile("cp.async.commit_group;\n");
    load_W(1);            asm volatile("cp.async.commit_group;\n");
    load_W(2); load_A(1); asm volatile("cp.async.commit_group;\n");
    load_W(3);            asm volatile("cp.async.commit_group;\n");

    float acc[2][4][4];
#pragma unroll
    for (int mt = 0; mt < 2; mt++)
#pragma unroll
        for (int nt = 0; nt < 4; nt++)
#pragma unroll
            for (int i = 0; i < 4; i++) acc[mt][nt][i] = 0.f;

#pragma unroll 1
    for (int ip = 0; ip < NPAIR; ip++) {
        // committed = 4+2*ip; wait leaves <=2 pending -> groups 0..2*ip+1 done
        // -> W stages 0..2*ip+1 and A superslots 0..ip landed.
        asm volatile("cp.async.wait_group %0;\n" :: "n"(2));
        __syncthreads();   // frees W slots (2ip-2,2ip-1)%6 and A slot (ip-1)%3

        if (2 * ip + 4 < NSTEP) load_W(2 * ip + 4);
        if (ip + 2 < NPAIR)     load_A(ip + 2);
        asm volatile("cp.async.commit_group;\n");      // commit EVERY iter (FIFO)
        if (2 * ip + 5 < NSTEP) load_W(2 * ip + 5);
        asm volatile("cp.async.commit_group;\n");

        // ---- MMA on stages 2*ip and 2*ip+1 ----
        const uint32_t* As = &sA[(ip % 3) * ASS_U];
#pragma unroll
        for (int ps = 0; ps < 2; ps++) {
            const int st = 2 * ip + ps;
            const float* ws = &sW[(st % WDEPTH) * WSTG_U];
            uint32_t ah[2][4], al[2][4];
#pragma unroll
            for (int mt = 0; mt < 2; mt++) {
                int mb = mt * 16;
                int ob = ps * 8;
                ah[mt][0] = As[(mb + g) * A_RSTR + ob + q];
                ah[mt][1] = As[(mb + g + 8) * A_RSTR + ob + q];
                ah[mt][2] = As[(mb + g) * A_RSTR + ob + q + 4];
                ah[mt][3] = As[(mb + g + 8) * A_RSTR + ob + q + 4];
                al[mt][0] = As[(mb + g) * A_RSTR + 16 + ob + q];
                al[mt][1] = As[(mb + g + 8) * A_RSTR + 16 + ob + q];
                al[mt][2] = As[(mb + g) * A_RSTR + 16 + ob + q + 4];
                al[mt][3] = As[(mb + g + 8) * A_RSTR + 16 + ob + q + 4];
            }
#pragma unroll
            for (int nt = 0; nt < 4; nt++) {
                int nc = warp * 32 + nt * 8 + g;
                float e0 = ws[(2 * q) * W_RSTR + nc];
                float o0 = ws[(2 * q + 1) * W_RSTR + nc];
                float e1 = ws[(2 * q + 8) * W_RSTR + nc];
                float o1 = ws[(2 * q + 9) * W_RSTR + nc];
                uint32_t bh[2], bl[2];
                split2(e0, o0, bh[0], bl[0]);
                split2(e1, o1, bh[1], bl[1]);
#pragma unroll
                for (int mt = 0; mt < 2; mt++) {
                    mma16816(acc[mt][nt], ah[mt], bh);   // hi*hi
                    mma16816(acc[mt][nt], ah[mt], bl);   // hi*lo
                    mma16816(acc[mt][nt], al[mt], bh);   // lo*hi
                }
            }
        }
    }

    // ---- store ----
#pragma unroll
    for (int mt = 0; mt < 2; mt++)
#pragma unroll
        for (int nt = 0; nt < 4; nt++) {
            int m = mt * 16 + g;
            int n = c0 + warp * 32 + nt * 8 + 2 * q;
            if (WHICH == 0) {
                size_t b0 = ((size_t)(s * 32 + m)) * N + n;
                g_part1[b0]     = acc[mt][nt][0];
                g_part1[b0 + 1] = acc[mt][nt][1];
                size_t b1 = b0 + (size_t)8 * N;
                g_part1[b1]     = acc[mt][nt][2];
                g_part1[b1 + 1] = acc[mt][nt][3];
            } else {
                float bb0 = bias[n], bb1 = bias[n + 1];
                size_t b0 = (size_t)m * N + n;
                g_y[b0]     = acc[mt][nt][0] + bb0;
                g_y[b0 + 1] = acc[mt][nt][1] + bb1;
                size_t b1 = b0 + (size_t)8 * N;
                g_y[b1]     = acc[mt][nt][2] + bb0;
                g_y[b1 + 1] = acc[mt][nt][3] + bb1;
            }
        }
}

// ---------------- reduce + bias + exact GELU -> packed h ---------------------
__global__ void __launch_bounds__(256) reduce_gelu(const float* __restrict__ b1) {
    int gid = blockIdx.x * 256 + threadIdx.x;        // m*1024 + kp
    int m = gid >> 10, kp = gid & 1023;
    float2 sum = *(const float2*)&b1[2 * kp];
#pragma unroll 8
    for (int s = 0; s < NS1; s++) {
        float2 v = *(const float2*)&g_part1[((size_t)(s * 32 + m)) * HID + 2 * kp];
        sum.x += v.x; sum.y += v.y;
    }
    float h0 = 0.5f * sum.x * (1.0f + erff(sum.x * 0.70710678118654752f));
    float h1 = 0.5f * sum.y * (1.0f + erff(sum.y * 0.70710678118654752f));
    uint32_t h, l;
    split2(h0, h1, h, l);
    g_hp_hi[gid] = h;
    g_hp_lo[gid] = l;
}

// ---------------- Gram partials: Gp[b*4+s] = A_chunk^T A_chunk ---------------
__global__ void __launch_bounds__(256) gram_kernel() {
    __shared__ __align__(16) float sh[64][36];
    const int b = blockIdx.x >> 2, s = blockIdx.x & 3;
    const int t = threadIdx.x;
    const int i  = t >> 3;
    const int j0 = (t * 4) & 31;
    float a0 = 0.f, a1 = 0.f, a2 = 0.f, a3 = 0.f;
    for (int chunk = 0; chunk < 8; chunk++) {
        int rowbase = s * 512 + chunk * 64;
#pragma unroll
        for (int l = 0; l < 8; l++) {
            int idx = l * 256 + t;
            int rl = idx >> 5, c = idx & 31;
            sh[rl][c] = g_y[(size_t)b * NOUT + (rowbase + rl) * 32 + c];
        }
        __syncthreads();
#pragma unroll 16
        for (int kk = 0; kk < 64; kk++) {
            float ai = sh[kk][i];
            float4 aj = *reinterpret_cast<const float4*>(&sh[kk][j0]);
            a0 += ai * aj.x; a1 += ai * aj.y; a2 += ai * aj.z; a3 += ai * aj.w;
        }
        __syncthreads();
    }
    size_t o = (size_t)(b * 4 + s) * 1024 + i * 32 + j0;
    g_Gp[o] = a0; g_Gp[o + 1] = a1; g_Gp[o + 2] = a2; g_Gp[o + 3] = a3;
}

// ---------------- Householder QR recurrence in 64-dim coefficient space ------
__global__ void __launch_bounds__(32) qr_recur() {
    const int b = blockIdx.x;
    const int t = threadIdx.x;
    __shared__ float sT[32][33];
    __shared__ float Vp[32][32], Vq[32][32], GH[32][32], TH[32][32];
    __shared__ float stau[32];
    __shared__ float pj[32], qj[32], spv[32], sqv[32];

    float rG[32], rT[32];
    for (int j = 0; j < 32; j++) {
        float g = 0.f;
#pragma unroll
        for (int s = 0; s < 4; s++) g += g_Gp[(size_t)(b * 4 + s) * 1024 + t * 32 + j];
        rG[j] = g;
        float tv = g_y[(size_t)b * NOUT + t * 32 + j];
        rT[j] = tv;
        sT[t][j] = tv;
    }
    __syncwarp();

    float p[32], q[32];
#pragma unroll
    for (int r = 0; r < 32; r++) { p[r] = (r == t) ? 1.f : 0.f; q[r] = 0.f; }

    for (int j = 0; j < 32; j++) {
        if (t == j) {
#pragma unroll
            for (int r = 0; r < 32; r++) { pj[r] = p[r]; qj[r] = q[r]; }
        }
        __syncwarp();
        float u = 0.f, gp = 0.f;
#pragma unroll
        for (int r = 0; r < 32; r++) { u += rT[r] * pj[r]; gp += rG[r] * pj[r]; }
        float h = u + qj[t];
        float term  = pj[t] * gp + qj[t] * (2.f * u + qj[t]);
        float hterm = (t < j) ? h * h : 0.f;
#pragma unroll
        for (int off = 16; off; off >>= 1) {
            term  += __shfl_xor_sync(0xffffffffu, term, off);
            hterm += __shfl_xor_sync(0xffffffffu, hterm, off);
        }
        float sigma = term - hterm;
        float alpha = __shfl_sync(0xffffffffu, h, j);
        float nrm = sqrtf(fmaxf(sigma, 0.f));
        float beta = (alpha >= 0.f) ? -nrm : nrm;
        float inv  = 1.f / (alpha - beta);
        float tauj = (beta - alpha) / beta;
        float pv = pj[t] * inv;
        float qv;
        if (t < j)       qv = (qj[t] - h) * inv;
        else if (t == j) qv = (qj[t] - beta) * inv;
        else             qv = qj[t] * inv;
        spv[t] = pv; sqv[t] = qv;
        Vp[j][t] = pv; Vq[j][t] = qv;
        if (t == 0) stau[j] = tauj;
        __syncwarp();
        float tpv = 0.f, gpv = 0.f, ttqv = 0.f;
#pragma unroll
        for (int r = 0; r < 32; r++) {
            tpv  += rT[r] * spv[r];
            gpv  += rG[r] * spv[r];
            ttqv += sT[r][t] * sqv[r];
        }
        GH[j][t] = gpv + ttqv;
        TH[j][t] = tpv + sqv[t];
        __syncwarp();
        if (t > j) {
            float w = 0.f;
#pragma unroll
            for (int r = 0; r < 32; r++) w += GH[j][r] * p[r] + TH[j][r] * q[r];
            float sc = tauj * w;
#pragma unroll
            for (int r = 0; r < 32; r++) { p[r] -= sc * Vp[j][r]; q[r] -= sc * Vq[j][r]; }
        }
        __syncwarp();
    }

#pragma unroll
    for (int r = 0; r < 32; r++) { p[r] = 0.f; q[r] = (r == t) ? 1.f : 0.f; }
    for (int j = 31; j >= 0; j--) {
        float w = 0.f;
#pragma unroll
        for (int r = 0; r < 32; r++) w += GH[j][r] * p[r] + TH[j][r] * q[r];
        float sc = stau[j] * w;
#pragma unroll
        for (int r = 0; r < 32; r++) { p[r] -= sc * Vp[j][r]; q[r] -= sc * Vq[j][r]; }
    }
#pragma unroll
    for (int r = 0; r < 32; r++) {
        g_P [(size_t)b * 1024 + r * 32 + t] = p[r];
        g_Qc[(size_t)b * 1024 + r * 32 + t] = q[r];
    }
}

// ---------------- Q = A P + E Qc ---------------------------------------------
__global__ void __launch_bounds__(256) formq(float* __restrict__ out) {
    __shared__ float sA[64][33];
    __shared__ float sP[32][33], sQ[32][33];
    const int b = blockIdx.y, rb = blockIdx.x;
    const int t = threadIdx.x;
    const int w = t >> 5, lane = t & 31;
#pragma unroll
    for (int l = 0; l < 8; l++) {
        int idx = l * 256 + t;
        int rl = idx >> 5, c = idx & 31;
        sA[rl][c] = g_y[(size_t)b * NOUT + (rb * 64 + rl) * 32 + c];
    }
#pragma unroll
    for (int l = 0; l < 4; l++) {
        int idx = l * 256 + t;
        int k = idx >> 5, c = idx & 31;
        sP[k][c] = g_P [(size_t)b * 1024 + idx];
        sQ[k][c] = g_Qc[(size_t)b * 1024 + idx];
    }
    __syncthreads();
#pragma unroll
    for (int rr = 0; rr < 8; rr++) {
        int rl = w * 8 + rr;
        float acc = 0.f;
#pragma unroll
        for (int k = 0; k < 32; k++) acc += sA[rl][k] * sP[k][lane];
        int rg = rb * 64 + rl;
        if (rg < 32) acc += sQ[rg][lane];
        out[(size_t)b * NOUT + rg * 32 + lane] = acc;
    }
}

// ---------------- launch -----------------------------------------------------
extern "C" void kernel_launch(void* const* d_in, const int* in_sizes, int n_in,
                              void* d_out, int out_size) {
    const float* x  = (const float*)d_in[0];
    const float* W1 = (const float*)d_in[1];
    const float* b1 = (const float*)d_in[2];
    const float* W2 = (const float*)d_in[3];
    const float* b2 = (const float*)d_in[4];
    float* out = (float*)d_out;
    (void)in_sizes; (void)n_in; (void)out_size;

    pack_x<<<(NB * K1 / 2) / 256, 256>>>(x);
    mma_gemm<HID, K1, K1 / NS1, 0><<<dim3(HID / NCOL, NS1), 256>>>(W1, b1);
    reduce_gelu<<<(NB * HID / 2) / 256, 256>>>(b1);
    mma_gemm<NOUT, HID, HID, 1><<<dim3(NOUT / NCOL, 1), 256>>>(W2, b2);
    gram_kernel<<<NB * 4, 256>>>();
    qr_recur<<<NB, 32>>>();
    formq<<<dim3(32, NB), 256>>>(out);
}